// round 5
// baseline (speedup 1.0000x reference)
#include <cuda_runtime.h>

// FocalLoss: loss = sum_b mean_a [ w[a] * (1-p)^2 * BCE(clamp(p), t) ]
// inputs [B, A] f32, targets [A, B] i32 (0/1), w [A] f32 -> scalar f32
// Mainloop is at the HBM floor (~50us for 320MB). Finalize reduces 3907
// partials (padded to 4096, tail stays 0 from static zero-init) with
// vectorized float4 loads so it is one-memory-latency cheap.
constexpr int BVAL = 1000000;
constexpr int AVAL = 40;
constexpr float EPSF = 1e-12f;
constexpr int TPB = 256;
constexpr int GRID = (BVAL + TPB - 1) / TPB;   // 3907
constexpr int PARTIALS_PAD = 4096;             // 256 threads * 4 float4 * 4

__device__ float g_partials[PARTIALS_PAD];     // zero-init at load; [GRID,4096) never written

__global__ void __launch_bounds__(TPB) focal_main_kernel(
    const float* __restrict__ inputs,
    const int*   __restrict__ targets,
    const float* __restrict__ w)
{
    __shared__ float sw[AVAL];
    int tid = threadIdx.x;
    if (tid < AVAL) sw[tid] = w[tid];
    __syncthreads();

    int b = blockIdx.x * TPB + tid;
    float acc = 0.0f;
    if (b < BVAL) {
        const float4* row = reinterpret_cast<const float4*>(inputs + (long)b * AVAL);
        #pragma unroll
        for (int a4 = 0; a4 < AVAL / 4; a4++) {
            float4 p4 = __ldg(row + a4);
            float pv[4] = {p4.x, p4.y, p4.z, p4.w};
            #pragma unroll
            for (int j = 0; j < 4; j++) {
                int a = a4 * 4 + j;
                int t = __ldg(targets + (long)a * BVAL + b);  // coalesced per a
                float p  = pv[j];
                float pc = fminf(fmaxf(p, EPSF), 1.0f - EPSF);
                float arg = t ? pc : (1.0f - pc);   // t is 0/1: one log suffices
                float bce = -__logf(arg);           // MUFU.LG2: stays HBM-bound
                float om  = 1.0f - p;               // focal weight uses UNCLAMPED p
                acc = fmaf(sw[a] * om * om, bce, acc);
            }
        }
    }

    // intra-warp reduce
    #pragma unroll
    for (int off = 16; off; off >>= 1)
        acc += __shfl_down_sync(0xffffffffu, acc, off);

    __shared__ float warpsum[TPB / 32];
    if ((tid & 31) == 0) warpsum[tid >> 5] = acc;
    __syncthreads();

    if (tid == 0) {
        float v = 0.0f;
        #pragma unroll
        for (int i = 0; i < TPB / 32; i++) v += warpsum[i];
        g_partials[blockIdx.x] = v;   // plain store, overwritten every launch
    }
}

__global__ void __launch_bounds__(TPB) finalize_kernel(float* __restrict__ out)
{
    int tid = threadIdx.x;
    const float4* p4 = reinterpret_cast<const float4*>(g_partials);

    // 4 independent float4 loads per thread -> all in flight simultaneously
    float4 v0 = p4[tid];
    float4 v1 = p4[tid + TPB];
    float4 v2 = p4[tid + 2 * TPB];
    float4 v3 = p4[tid + 3 * TPB];

    double d = ((double)v0.x + v0.y) + ((double)v0.z + v0.w);
    d += ((double)v1.x + v1.y) + ((double)v1.z + v1.w);
    d += ((double)v2.x + v2.y) + ((double)v2.z + v2.w);
    d += ((double)v3.x + v3.y) + ((double)v3.z + v3.w);

    #pragma unroll
    for (int off = 16; off; off >>= 1)
        d += __shfl_down_sync(0xffffffffu, d, off);

    __shared__ double dws[TPB / 32];
    if ((tid & 31) == 0) dws[tid >> 5] = d;
    __syncthreads();
    if (tid == 0) {
        double tot = 0.0;
        #pragma unroll
        for (int i = 0; i < TPB / 32; i++) tot += dws[i];
        out[0] = (float)(tot * (1.0 / (double)AVAL));
    }
}

extern "C" void kernel_launch(void* const* d_in, const int* in_sizes, int n_in,
                              void* d_out, int out_size)
{
    const float* inputs  = (const float*)d_in[0];   // [B, A]
    const int*   targets = (const int*)  d_in[1];   // [A, B]
    const float* weights = (const float*)d_in[2];   // [A]
    focal_main_kernel<<<GRID, TPB>>>(inputs, targets, weights);
    finalize_kernel<<<1, TPB>>>((float*)d_out);
}